// round 8
// baseline (speedup 1.0000x reference)
#include <cuda_runtime.h>
#include <cuda_bf16.h>

// Problem constants (B=2, T=256, E=256, H=4)
#define E_DIM  256
#define H_DIM  4
#define EH_DIM 1024
#define BT_DIM 512
#define SPLITK 32
#define PCHUNK 32           // EH_DIM / SPLITK

typedef unsigned long long u64;

// Packed fp32x2 helpers (sm_100+): one instruction, two fp32 FMAs.
#define PACK2(d, lo, hi) asm("mov.b64 %0, {%1, %2};" : "=l"(d) : "f"(lo), "f"(hi))
#define FMA2(d, a, b)    asm("fma.rn.f32x2 %0, %1, %2, %0;" : "+l"(d) : "l"(a), "l"(b))
#define UNPACK2(lo, hi, s) asm("mov.b64 {%0, %1}, %2;" : "=f"(lo), "=f"(hi) : "l"(s))

// Split-K partials for C[f][e] (plain stores -> deterministic), then reduced.
__device__ float g_Cp[SPLITK][E_DIM * E_DIM];   // 8 MB
__device__ float g_C[E_DIM * E_DIM];            // 256 KB

// ---------------------------------------------------------------------------
// Kernel 1: partial C.  C[f,e] = sum_p Wv[c(p), f] * Wp[e, p]
//   p = d*H + h (Wp-native), c(p) = (p&3)*256 + (p>>2).  Both loads coalesced.
// 64x64 tile, 4x4 micro-tile (f32x2-packed along f), 256 thr, grid (4,4,32).
// ---------------------------------------------------------------------------
__global__ __launch_bounds__(256) void build_C_kernel(
    const float* __restrict__ Wv,   // [EH, E] row-major
    const float* __restrict__ Wp)   // [E, EH] row-major
{
    __shared__ __align__(16) float sA[16][64];   // [p_local][f_local]
    __shared__ __align__(16) float sB[16][68];   // [p_local][e_local] (pad)

    const int tid = threadIdx.x;
    const int tx  = tid & 15;       // f group
    const int ty  = tid >> 4;       // e group
    const int f0  = blockIdx.x * 64;
    const int e0  = blockIdx.y * 64;
    const int p0  = blockIdx.z * PCHUNK;

    u64 acc01[4], acc23[4];
    #pragma unroll
    for (int j = 0; j < 4; j++) { PACK2(acc01[j], 0.0f, 0.0f); PACK2(acc23[j], 0.0f, 0.0f); }

    const int lA_pc = tid >> 4;            // 0..15
    const int lA_f4 = (tid & 15) * 4;
    const int lB_e  = tid >> 2;            // 0..63
    const int lB_p4 = (tid & 3) * 4;

    // --- prefetch iter 0 ---
    float4 pa, pb;
    {
        int p = p0 + lA_pc;
        int c = ((p & 3) << 8) + (p >> 2);
        pa = *(const float4*)&Wv[c * E_DIM + f0 + lA_f4];
        pb = *(const float4*)&Wp[(e0 + lB_e) * EH_DIM + p0 + lB_p4];
    }

    #pragma unroll
    for (int it = 0; it < PCHUNK / 16; it++) {
        *(float4*)&sA[lA_pc][lA_f4] = pa;
        sB[lB_p4 + 0][lB_e] = pb.x;
        sB[lB_p4 + 1][lB_e] = pb.y;
        sB[lB_p4 + 2][lB_e] = pb.z;
        sB[lB_p4 + 3][lB_e] = pb.w;
        __syncthreads();

        if (it < PCHUNK / 16 - 1) {   // prefetch next tile (hidden under compute)
            int p = p0 + (it + 1) * 16 + lA_pc;
            int c = ((p & 3) << 8) + (p >> 2);
            pa = *(const float4*)&Wv[c * E_DIM + f0 + lA_f4];
            pb = *(const float4*)&Wp[(e0 + lB_e) * EH_DIM + p0 + (it + 1) * 16 + lB_p4];
        }

        #pragma unroll
        for (int ps = 0; ps < 16; ps++) {
            float4 a = *(float4*)&sA[ps][tx * 4];
            float4 b = *(float4*)&sB[ps][ty * 4];
            u64 a01, a23, bd0, bd1, bd2, bd3;
            PACK2(a01, a.x, a.y);
            PACK2(a23, a.z, a.w);
            PACK2(bd0, b.x, b.x); FMA2(acc01[0], a01, bd0); FMA2(acc23[0], a23, bd0);
            PACK2(bd1, b.y, b.y); FMA2(acc01[1], a01, bd1); FMA2(acc23[1], a23, bd1);
            PACK2(bd2, b.z, b.z); FMA2(acc01[2], a01, bd2); FMA2(acc23[2], a23, bd2);
            PACK2(bd3, b.w, b.w); FMA2(acc01[3], a01, bd3); FMA2(acc23[3], a23, bd3);
        }
        __syncthreads();
    }

    // epilogue: unpack 16 results, store 4 x STG.128
    float r[4][4];
    #pragma unroll
    for (int j = 0; j < 4; j++) {
        UNPACK2(r[0][j], r[1][j], acc01[j]);
        UNPACK2(r[2][j], r[3][j], acc23[j]);
    }
    float* dst = &g_Cp[blockIdx.z][0];
    #pragma unroll
    for (int i = 0; i < 4; i++) {
        int f = f0 + tx * 4 + i;
        *(float4*)&dst[f * E_DIM + e0 + ty * 4] =
            make_float4(r[i][0], r[i][1], r[i][2], r[i][3]);
    }
}

// ---------------------------------------------------------------------------
// Kernel 2: g_C = sum_z g_Cp[z]   (fixed z order -> deterministic)
// 128 blocks x 128 threads, one float4 per thread, 8-deep MLP load batches.
// ---------------------------------------------------------------------------
__global__ __launch_bounds__(128) void reduce_C_kernel()
{
    int idx4 = (blockIdx.x * 128 + threadIdx.x) * 4;   // covers 65536 floats
    float4 s = make_float4(0.f, 0.f, 0.f, 0.f);
    #pragma unroll
    for (int z0 = 0; z0 < SPLITK; z0 += 8) {
        float4 v[8];
        #pragma unroll
        for (int z = 0; z < 8; z++)
            v[z] = *(const float4*)&g_Cp[z0 + z][idx4];
        #pragma unroll
        for (int z = 0; z < 8; z++) {
            s.x += v[z].x; s.y += v[z].y; s.z += v[z].z; s.w += v[z].w;
        }
    }
    *(float4*)&g_C[idx4] = s;
}

// ---------------------------------------------------------------------------
// Kernel 3: out[m,e] = sum_f values[m,f] * C[f,e]
// 32x32 tile, 2x2 micro (f32x2 along m), 256 thr, grid (8,16) = 128 CTAs.
// sV transposed to [f][m] so both operands read as float2.
// ---------------------------------------------------------------------------
__global__ __launch_bounds__(256) void gemm_out_kernel(
    const float* __restrict__ values,   // [BT, E]
    float* __restrict__ out)            // [BT, E]
{
    __shared__ __align__(8) float sV[16][34];   // [f_local][m]
    __shared__ __align__(8) float sC[16][34];   // [f_local][e]

    const int tid = threadIdx.x;
    const int tx  = tid & 15;      // e pair
    const int ty  = tid >> 4;      // m pair
    const int e0  = blockIdx.x * 32;
    const int m0  = blockIdx.y * 32;

    u64 accj0, accj1;              // (m0,m1) packed, for e=2tx and e=2tx+1
    PACK2(accj0, 0.0f, 0.0f);
    PACK2(accj1, 0.0f, 0.0f);

    const int lV_m  = tid >> 3;           // 0..31
    const int lV_f2 = (tid & 7) * 2;      // 0..14
    const int lC_f  = tid >> 4;           // 0..15
    const int lC_e2 = (tid & 15) * 2;     // 0..30

    float2 pv = *(const float2*)&values[(m0 + lV_m) * E_DIM + lV_f2];
    float2 pc = *(const float2*)&g_C[lC_f * E_DIM + e0 + lC_e2];

    #pragma unroll
    for (int it = 0; it < E_DIM / 16; it++) {
        sV[lV_f2][lV_m]     = pv.x;       // transposed store
        sV[lV_f2 + 1][lV_m] = pv.y;
        *(float2*)&sC[lC_f][lC_e2] = pc;
        __syncthreads();

        if (it < E_DIM / 16 - 1) {
            int f0 = (it + 1) * 16;
            pv = *(const float2*)&values[(m0 + lV_m) * E_DIM + f0 + lV_f2];
            pc = *(const float2*)&g_C[(f0 + lC_f) * E_DIM + e0 + lC_e2];
        }

        #pragma unroll
        for (int ps = 0; ps < 16; ps++) {
            float2 a = *(float2*)&sV[ps][ty * 2];   // (m0, m1)
            float2 b = *(float2*)&sC[ps][tx * 2];   // (e0, e1)
            u64 a01, bd0, bd1;
            PACK2(a01, a.x, a.y);
            PACK2(bd0, b.x, b.x); FMA2(accj0, a01, bd0);
            PACK2(bd1, b.y, b.y); FMA2(accj1, a01, bd1);
        }
        __syncthreads();
    }

    float o00, o10, o01, o11;
    UNPACK2(o00, o10, accj0);
    UNPACK2(o01, o11, accj1);
    *(float2*)&out[(m0 + ty * 2) * E_DIM + e0 + tx * 2]     = make_float2(o00, o01);
    *(float2*)&out[(m0 + ty * 2 + 1) * E_DIM + e0 + tx * 2] = make_float2(o10, o11);
}

// ---------------------------------------------------------------------------
// softmax over w sums to 1 => out = Vh; only values, Wv, Wp matter.
// Inputs: 0=pos_emb, 1=values, 2=ln_w, 3=ln_b, 4=Wq, 5=Wk, 6=Wv, 7=Wp.
// ---------------------------------------------------------------------------
extern "C" void kernel_launch(void* const* d_in, const int* in_sizes, int n_in,
                              void* d_out, int out_size)
{
    const float* values = (const float*)d_in[1];
    const float* Wv     = (const float*)d_in[6];
    const float* Wp     = (const float*)d_in[7];
    float* out          = (float*)d_out;

    build_C_kernel<<<dim3(4, 4, SPLITK), 256>>>(Wv, Wp);
    reduce_C_kernel<<<128, 128>>>();
    gemm_out_kernel<<<dim3(8, 16), 256>>>(values, out);
}